// round 4
// baseline (speedup 1.0000x reference)
#include <cuda_runtime.h>
#include <math.h>

#define D 8192
#define M_TIME 16
#define KWTA_K (D / 8)
#define ROWS 8                      // rows per block = warps per block
#define GTHREADS 256
#define CHUNK 512                   // floats per row per stage
#define C4 (CHUNK / 4)              // 128 float4 per row per stage
#define NCHUNK (D / CHUNK)          // 16
#define NSTAGE 4
#define STAGE_F4 (ROWS * C4)        // 1024 float4 per stage (16 KB)
#define SMEM_BYTES (NSTAGE * STAGE_F4 * 16)   // 64 KB ring

// Scratch (device globals — no allocation allowed)
__device__ float g_x[D];
__device__ float g_rpre[D];
__device__ float g_k[D];
__device__ float g_v[D];
__device__ float g_y[D];
__device__ float g_h[D];

__device__ __forceinline__ float softplusf(float x) {
    if (x > 20.f) return x;
    if (x < -20.f) return expf(x);
    return log1pf(expf(x));
}

__device__ __forceinline__ void cp_async16(void* smem_dst, const void* gmem_src) {
    unsigned saddr = (unsigned)__cvta_generic_to_shared(smem_dst);
    asm volatile("cp.async.cg.shared.global [%0], [%1], 16;\n"
                 :: "r"(saddr), "l"(gmem_src));
}
__device__ __forceinline__ void cp_commit() {
    asm volatile("cp.async.commit_group;\n");
}
template <int N>
__device__ __forceinline__ void cp_wait() {
    asm volatile("cp.async.wait_group %0;\n" :: "n"(N));
}

// ---------------------------------------------------------------------------
// K0: x = rmsnorm(x_in + pred) * g_norm     (1 block, 1024 threads)
// ---------------------------------------------------------------------------
__global__ void rmsnorm_kernel(const float* __restrict__ x_in,
                               const float* __restrict__ pred,
                               const float* __restrict__ g_norm) {
    __shared__ float red[1024];
    float s = 0.f;
    for (int i = threadIdx.x; i < D; i += 1024) {
        float t = x_in[i] + pred[i];
        s += t * t;
    }
    red[threadIdx.x] = s;
    __syncthreads();
    for (int o = 512; o > 0; o >>= 1) {
        if (threadIdx.x < o) red[threadIdx.x] += red[threadIdx.x + o];
        __syncthreads();
    }
    float scale = rsqrtf(red[0] / (float)D + 1e-6f);
    for (int i = threadIdx.x; i < D; i += 1024) {
        g_x[i] = (x_in[i] + pred[i]) * scale * g_norm[i];
    }
}

// ---------------------------------------------------------------------------
// Barrier-free GEMV pipeline.
// Warp w owns row (rowbase + w). Lane l owns float4 column slots l+32j
// (j=0..3) of each 512-float chunk. Each thread consumes ONLY the smem
// slots its own cp.asyncs wrote -> per-thread wait_group suffices, no
// __syncthreads in the mainloop. 4-stage ring, 3 stages in flight.
// ---------------------------------------------------------------------------
__device__ __forceinline__ void gemv_pipe(const float* __restrict__ W,
                                          const float* __restrict__ vec,
                                          int rowbase,
                                          float* __restrict__ dst,
                                          const float* __restrict__ add_src) {
    extern __shared__ float4 sbuf[];   // [NSTAGE][ROWS][C4]
    const int w = threadIdx.x >> 5;
    const int l = threadIdx.x & 31;
    const int row = rowbase + w;
    const float* wrow = W + (size_t)row * D;
    const float4* xv = (const float4*)vec;

    // Stage issue: 4 cp.asyncs per thread, one commit group per stage.
#define ISSUE_STAGE(s)                                                        \
    do {                                                                      \
        const float* _src = wrow + (s) * CHUNK + l * 4;                       \
        float4* _d = sbuf + ((s) & (NSTAGE - 1)) * STAGE_F4 + w * C4 + l;     \
        cp_async16(_d,      _src);                                            \
        cp_async16(_d + 32, _src + 128);                                      \
        cp_async16(_d + 64, _src + 256);                                      \
        cp_async16(_d + 96, _src + 384);                                      \
        cp_commit();                                                          \
    } while (0)

    ISSUE_STAGE(0);
    ISSUE_STAGE(1);
    ISSUE_STAGE(2);

    float acc0 = 0.f, acc1 = 0.f, acc2 = 0.f, acc3 = 0.f;

#pragma unroll
    for (int ci = 0; ci < NCHUNK; ci++) {
        if (ci + 3 < NCHUNK) ISSUE_STAGE(ci + 3);
        // wait until this thread's stage-ci group has landed
        const int rem = NCHUNK - ci;         // compile-time under unroll
        if (rem >= 4)      cp_wait<3>();
        else if (rem == 3) cp_wait<2>();
        else if (rem == 2) cp_wait<1>();
        else               cp_wait<0>();

        const float4* sb = sbuf + (ci & (NSTAGE - 1)) * STAGE_F4 + w * C4 + l;
        const float4* xc = xv + ci * C4 + l;
        float4 w0 = sb[0],  x0 = xc[0];
        float4 w1 = sb[32], x1 = xc[32];
        float4 w2 = sb[64], x2 = xc[64];
        float4 w3 = sb[96], x3 = xc[96];
        acc0 += w0.x * x0.x + w0.y * x0.y + w0.z * x0.z + w0.w * x0.w;
        acc1 += w1.x * x1.x + w1.y * x1.y + w1.z * x1.z + w1.w * x1.w;
        acc2 += w2.x * x2.x + w2.y * x2.y + w2.z * x2.z + w2.w * x2.w;
        acc3 += w3.x * x3.x + w3.y * x3.y + w3.z * x3.z + w3.w * x3.w;
    }
#undef ISSUE_STAGE

    float acc = (acc0 + acc1) + (acc2 + acc3);
#pragma unroll
    for (int o = 16; o > 0; o >>= 1)
        acc += __shfl_xor_sync(0xFFFFFFFFu, acc, o);

    if (l == 0) dst[row] = add_src ? (add_src[row] + acc) : acc;
}

// K1: fused Wr/Wk/Wv GEMV. grid.x = 3 * D/ROWS = 3072
__global__ void __launch_bounds__(GTHREADS) gemv3_kernel(const float* __restrict__ Wr,
                                                         const float* __restrict__ Wk,
                                                         const float* __restrict__ Wv) {
    const int blocks_per_mat = D / ROWS;  // 1024
    int mat = blockIdx.x / blocks_per_mat;
    int rowbase = (blockIdx.x % blocks_per_mat) * ROWS;
    const float* W = (mat == 0) ? Wr : ((mat == 1) ? Wk : Wv);
    float* dst = (mat == 0) ? g_rpre : ((mat == 1) ? g_k : g_v);
    gemv_pipe(W, g_x, rowbase, dst, nullptr);
}

// K3: h = x + Wo @ y. grid.x = D/ROWS = 1024
__global__ void __launch_bounds__(GTHREADS) gemv_o_kernel(const float* __restrict__ Wo) {
    int rowbase = blockIdx.x * ROWS;
    gemv_pipe(Wo, g_y, rowbase, g_h, g_x);
}

// ---------------------------------------------------------------------------
// K2: elementwise (decay, RoPE, Kalman gate) -> y
// ---------------------------------------------------------------------------
__global__ void elemwise_kernel(const float* __restrict__ step_pos,
                                const float* __restrict__ state_num,
                                const float* __restrict__ state_den,
                                const float* __restrict__ state_var,
                                const float* __restrict__ raw_decay,
                                const float* __restrict__ pn_param,
                                const float* __restrict__ on_param,
                                const float* __restrict__ W_time) {
    int i = blockIdx.x * 256 + threadIdx.x;
    if (i >= D) return;

    float k = g_k[i];
    float v = g_v[i];
    if (i < 2 * M_TIME) {
        int m = i >> 1;
        float th = step_pos[0] * W_time[m];
        float c, s;
        sincosf(th, &s, &c);
        float v0 = g_v[2 * m];
        float v1 = g_v[2 * m + 1];
        v = (i & 1) ? (v0 * s + v1 * c) : (v0 * c - v1 * s);
    }

    float sp = softplusf(raw_decay[i]);
    float rate = fmaxf(-sp, -30.f);
    float lam = fmaxf(expf(rate), 1e-6f);
    float pn = fminf(fmaxf(softplusf(pn_param[0]), 1e-6f), 1e4f);
    float on = fminf(fmaxf(softplusf(on_param[0]), 1e-6f), 1e4f);

    float sn = state_num[i] * lam;
    float sd = state_den[i] * lam;
    float sv = state_var[i] * lam * lam + pn;

    float r = 1.f / (1.f + expf(-g_rpre[i]));
    float w = expf(fminf(k, 30.f));
    float pred_state = sn / (sd + 1e-6f);
    float msg = w * v;
    float resid = msg - pred_state;
    float obs_var = expf(fminf(-k, 30.f)) * on + 1e-6f;
    float gain = sv / (sv + obs_var);
    gain = fminf(fmaxf(gain, 1e-6f), 1.f - 1e-6f);
    float new_state = pred_state + gain * resid;
    g_y[i] = r * new_state;
}

// ---------------------------------------------------------------------------
// K4: exact KWTA_K-th-largest (radix select) + threshold. 1 block, 1024 thr.
// ---------------------------------------------------------------------------
__global__ void topk_kernel(float* __restrict__ out) {
    __shared__ unsigned hist[256];
    __shared__ unsigned s_prefix;
    __shared__ int s_K;
    __shared__ float s_thresh;

    if (threadIdx.x == 0) { s_prefix = 0u; s_K = KWTA_K; }
    __syncthreads();

    for (int pass = 3; pass >= 0; pass--) {
        if (threadIdx.x < 256) hist[threadIdx.x] = 0u;
        __syncthreads();
        unsigned prefmask = (pass == 3) ? 0u : (0xFFFFFFFFu << ((pass + 1) * 8));
        unsigned pref = s_prefix;
        for (int i = threadIdx.x; i < D; i += 1024) {
            unsigned u = __float_as_uint(g_h[i]);
            unsigned key = (u & 0x80000000u) ? ~u : (u | 0x80000000u);
            if ((key & prefmask) == (pref & prefmask)) {
                atomicAdd(&hist[(key >> (pass * 8)) & 255u], 1u);
            }
        }
        __syncthreads();
        if (threadIdx.x == 0) {
            int K = s_K;
            unsigned cum = 0;
            int b = 255;
            for (; b >= 0; b--) {
                cum += hist[b];
                if ((int)cum >= K) break;
            }
            s_K = K - (int)(cum - hist[b]);
            s_prefix = s_prefix | ((unsigned)b << (pass * 8));
        }
        __syncthreads();
    }

    if (threadIdx.x == 0) {
        unsigned key = s_prefix;
        unsigned u = (key & 0x80000000u) ? (key ^ 0x80000000u) : ~key;
        s_thresh = __uint_as_float(u);
    }
    __syncthreads();

    float th = s_thresh;
    for (int i = threadIdx.x; i < D; i += 1024) {
        float h = g_h[i];
        out[i] = (h >= th) ? h : 0.f;
    }
}

// ---------------------------------------------------------------------------
// Launch
// ---------------------------------------------------------------------------
extern "C" void kernel_launch(void* const* d_in, const int* in_sizes, int n_in,
                              void* d_out, int out_size) {
    const float* x_in      = (const float*)d_in[0];
    const float* step_pos  = (const float*)d_in[1];
    const float* pred      = (const float*)d_in[2];
    const float* state_num = (const float*)d_in[3];
    const float* state_den = (const float*)d_in[4];
    const float* state_var = (const float*)d_in[5];
    const float* Wr        = (const float*)d_in[6];
    const float* Wk        = (const float*)d_in[7];
    const float* Wv        = (const float*)d_in[8];
    const float* Wo        = (const float*)d_in[9];
    const float* raw_decay = (const float*)d_in[10];
    const float* pn_param  = (const float*)d_in[11];
    const float* on_param  = (const float*)d_in[12];
    const float* g_norm    = (const float*)d_in[13];
    const float* W_time    = (const float*)d_in[14];
    float* out = (float*)d_out;

    cudaFuncSetAttribute(gemv3_kernel,
                         cudaFuncAttributeMaxDynamicSharedMemorySize, SMEM_BYTES);
    cudaFuncSetAttribute(gemv_o_kernel,
                         cudaFuncAttributeMaxDynamicSharedMemorySize, SMEM_BYTES);

    rmsnorm_kernel<<<1, 1024>>>(x_in, pred, g_norm);
    gemv3_kernel<<<3 * (D / ROWS), GTHREADS, SMEM_BYTES>>>(Wr, Wk, Wv);
    elemwise_kernel<<<D / 256, 256>>>(step_pos, state_num, state_den, state_var,
                                      raw_decay, pn_param, on_param, W_time);
    gemv_o_kernel<<<D / ROWS, GTHREADS, SMEM_BYTES>>>(Wo);
    topk_kernel<<<1, 1024>>>(out);
}